// round 1
// baseline (speedup 1.0000x reference)
#include <cuda_runtime.h>
#include <cuda_bf16.h>

#define D_MODEL 2048
#define RANK    64
#define VOCAB   50257
#define N_TOK   32

// scratch for per-token scalars s[n] (no device mallocs allowed)
__device__ float g_s[N_TOK];

// Kernel 1: s[n] = sum_d h[n,d] * (sum_r U[d,r] * S[r])
// One block, 1024 threads = 32 warps; warp w owns token w.
__global__ __launch_bounds__(1024, 1)
void fftlm_reduce_kernel(const float* __restrict__ h,
                         const float* __restrict__ U,
                         const float* __restrict__ S) {
    __shared__ float u[D_MODEL];
    __shared__ float s_sh[RANK];

    int tid = threadIdx.x;
    if (tid < RANK) s_sh[tid] = S[tid];
    __syncthreads();

    // u[d] = sum_r U[d*RANK + r] * S[r]  (U read once, fully coalesced per row)
    for (int d = tid; d < D_MODEL; d += 1024) {
        const float* Urow = U + (size_t)d * RANK;
        float acc = 0.f;
#pragma unroll
        for (int r = 0; r < RANK; r++) acc += Urow[r] * s_sh[r];
        u[d] = acc;
    }
    __syncthreads();

    int warp = tid >> 5;
    int lane = tid & 31;
    const float* hrow = h + (size_t)warp * D_MODEL;
    float acc = 0.f;
#pragma unroll 4
    for (int d = lane; d < D_MODEL; d += 32) acc += hrow[d] * u[d];
#pragma unroll
    for (int o = 16; o; o >>= 1) acc += __shfl_xor_sync(0xffffffffu, acc, o);
    if (lane == 0) g_s[warp] = acc;
}

// Kernel 2: out[n, v] = s[n] * (sum_r Vh[r, v])
// Pure streaming: read Vh column-sums (coalesced across v), write 32 rows.
__global__ __launch_bounds__(256)
void fftlm_outer_kernel(const float* __restrict__ Vh,
                        float* __restrict__ out) {
    __shared__ float s_sh[N_TOK];
    if (threadIdx.x < N_TOK) s_sh[threadIdx.x] = g_s[threadIdx.x];
    __syncthreads();

    int v = blockIdx.x * blockDim.x + threadIdx.x;
    if (v >= VOCAB) return;

    float w = 0.f;
#pragma unroll
    for (int r = 0; r < RANK; r++) w += Vh[(size_t)r * VOCAB + v];

#pragma unroll
    for (int n = 0; n < N_TOK; n++) out[(size_t)n * VOCAB + v] = s_sh[n] * w;
}

extern "C" void kernel_launch(void* const* d_in, const int* in_sizes, int n_in,
                              void* d_out, int out_size) {
    const float* h  = (const float*)d_in[0];  // (32, 2048)
    const float* U  = (const float*)d_in[1];  // (2048, 64)
    const float* S  = (const float*)d_in[2];  // (64,)
    const float* Vh = (const float*)d_in[3];  // (64, 50257)
    float* out = (float*)d_out;               // (32, 50257)

    fftlm_reduce_kernel<<<1, 1024>>>(h, U, S);

    int threads = 256;
    int blocks = (VOCAB + threads - 1) / threads;  // 197
    fftlm_outer_kernel<<<blocks, threads>>>(Vh, out);
}

// round 5
// speedup vs baseline: 6.8457x; 6.8457x over previous
#include <cuda_runtime.h>
#include <cuda_bf16.h>

#define D_MODEL 2048
#define RANK    64
#define VOCAB   50257
#define N_TOK   32

#define NBLK_PART 32          // 32 blocks x 64 d-rows each

// per-block partial sums of s[n]  [block][token] — deterministic, no atomics
__device__ float g_part[NBLK_PART * N_TOK];

// Kernel 1: partial s over d-slice [b*64, b*64+64):
//   u[d] = sum_r U[d,r]*S[r];  part[b][n] = sum_{d in slice} h[n,d]*u[d]
__global__ __launch_bounds__(256)
void fftlm_partial_kernel(const float* __restrict__ h,
                          const float* __restrict__ U,
                          const float* __restrict__ S) {
    __shared__ float sS[RANK];
    __shared__ float su[64];

    const int tid  = threadIdx.x;
    const int warp = tid >> 5;
    const int lane = tid & 31;
    const int dbase = blockIdx.x * 64;

    if (tid < RANK) sS[tid] = S[tid];
    __syncthreads();

    // 8 warps x 8 rows each: u[d] = dot(U[d,:], S)  (row = 64 floats, 2/lane)
#pragma unroll
    for (int k = 0; k < 8; k++) {
        int dl = warp * 8 + k;                  // local row 0..63
        const float* Ur = U + (size_t)(dbase + dl) * RANK;
        float v = Ur[lane] * sS[lane] + Ur[lane + 32] * sS[lane + 32];
#pragma unroll
        for (int o = 16; o; o >>= 1) v += __shfl_xor_sync(0xffffffffu, v, o);
        if (lane == 0) su[dl] = v;
    }
    __syncthreads();

    // 8 warps x 4 tokens each: part = dot(h[n, dbase:dbase+64], su)
#pragma unroll
    for (int k = 0; k < 4; k++) {
        int n = warp * 4 + k;
        const float* hr = h + (size_t)n * D_MODEL + dbase;
        float v = hr[lane] * su[lane] + hr[lane + 32] * su[lane + 32];
#pragma unroll
        for (int o = 16; o; o >>= 1) v += __shfl_xor_sync(0xffffffffu, v, o);
        if (lane == 0) g_part[blockIdx.x * N_TOK + n] = v;
    }
}

// Kernel 2: out[n, v] = s[n] * (sum_r Vh[r, v])
// 4 threads per column (each sums 16 ranks, scalar — rows are NOT 16B-aligned
// because VOCAB is odd), quad-butterfly combine, each thread stores 8 rows.
__global__ __launch_bounds__(256)
void fftlm_outer_kernel(const float* __restrict__ Vh,
                        float* __restrict__ out) {
    __shared__ float s_sh[N_TOK];
    if (threadIdx.x < N_TOK) {
        float acc = 0.f;
#pragma unroll
        for (int b = 0; b < NBLK_PART; b++) acc += g_part[b * N_TOK + threadIdx.x];
        s_sh[threadIdx.x] = acc;
    }
    __syncthreads();

    const int gid  = blockIdx.x * blockDim.x + threadIdx.x;
    const int col  = gid >> 2;      // vocab column
    const int sub  = gid & 3;       // quarter of the rank axis
    const int lane = threadIdx.x & 31;
    const unsigned qmask = 0xFu << (lane & 28);   // the 4 lanes of this quad

    if (col >= VOCAB) return;

    const int r0 = sub * 16;
    float acc = 0.f;
#pragma unroll
    for (int i = 0; i < 16; i++)
        acc += Vh[(size_t)(r0 + i) * VOCAB + col];

    // butterfly within quad -> every lane holds the full rank sum
#pragma unroll
    for (int m = 1; m <= 2; m <<= 1)
        acc += __shfl_xor_sync(qmask, acc, m);

    // each sub-thread stores 8 of the 32 token rows
#pragma unroll
    for (int j = 0; j < 8; j++) {
        int n = sub * 8 + j;
        out[(size_t)n * VOCAB + col] = s_sh[n] * acc;
    }
}

extern "C" void kernel_launch(void* const* d_in, const int* in_sizes, int n_in,
                              void* d_out, int out_size) {
    const float* h  = (const float*)d_in[0];  // (32, 2048)
    const float* U  = (const float*)d_in[1];  // (2048, 64)
    const float* S  = (const float*)d_in[2];  // (64,)
    const float* Vh = (const float*)d_in[3];  // (64, 50257)
    float* out = (float*)d_out;               // (32, 50257)

    fftlm_partial_kernel<<<NBLK_PART, 256>>>(h, U, S);

    const int threads = 256;
    const int blocks = (VOCAB * 4 + threads - 1) / threads;  // 786
    fftlm_outer_kernel<<<blocks, threads>>>(Vh, out);
}

// round 6
// speedup vs baseline: 7.5484x; 1.1026x over previous
#include <cuda_runtime.h>
#include <cuda_bf16.h>

#define D_MODEL 2048
#define RANK    64
#define VOCAB   50257
#define N_TOK   32

#define NBLK_PART 32          // 32 blocks x 64 d-rows each

__device__ float g_part[NBLK_PART * N_TOK];  // per-block partials
__device__ float g_s[N_TOK];                 // final s[n]
__device__ int   g_count;                    // zero-initialized; self-resetting

// Kernel 1: partial s over d-slice; the last block folds partials into g_s.
//   u[d] = sum_r U[d,r]*S[r];  part[b][n] = sum_{d in slice} h[n,d]*u[d]
__global__ __launch_bounds__(256)
void fftlm_partial_kernel(const float* __restrict__ h,
                          const float* __restrict__ U,
                          const float* __restrict__ S) {
    __shared__ float sS[RANK];
    __shared__ float su[64];
    __shared__ int   is_last;

    const int tid  = threadIdx.x;
    const int warp = tid >> 5;
    const int lane = tid & 31;
    const int dbase = blockIdx.x * 64;

    if (tid < RANK) sS[tid] = S[tid];
    __syncthreads();

    // 8 warps x 8 rows each: u[d] = dot(U[d,:], S)
#pragma unroll
    for (int k = 0; k < 8; k++) {
        int dl = warp * 8 + k;
        const float* Ur = U + (size_t)(dbase + dl) * RANK;
        float v = Ur[lane] * sS[lane] + Ur[lane + 32] * sS[lane + 32];
#pragma unroll
        for (int o = 16; o; o >>= 1) v += __shfl_xor_sync(0xffffffffu, v, o);
        if (lane == 0) su[dl] = v;
    }
    __syncthreads();

    // 8 warps x 4 tokens each: part = dot(h[n, dbase:dbase+64], su)
#pragma unroll
    for (int k = 0; k < 4; k++) {
        int n = warp * 4 + k;
        const float* hr = h + (size_t)n * D_MODEL + dbase;
        float v = hr[lane] * su[lane] + hr[lane + 32] * su[lane + 32];
#pragma unroll
        for (int o = 16; o; o >>= 1) v += __shfl_xor_sync(0xffffffffu, v, o);
        if (lane == 0) g_part[blockIdx.x * N_TOK + n] = v;
    }

    // last-block-done deterministic fold (who = nondet, what = deterministic)
    __threadfence();
    if (tid == 0) is_last = (atomicAdd(&g_count, 1) == NBLK_PART - 1);
    __syncthreads();
    if (is_last) {
        if (tid < N_TOK) {
            float acc = 0.f;
#pragma unroll
            for (int b = 0; b < NBLK_PART; b++) acc += g_part[b * N_TOK + tid];
            g_s[tid] = acc;
        }
        if (tid == 0) g_count = 0;   // self-reset for next graph replay
    }
}

// Kernel 2: out[n, v] = s[n] * (sum_r Vh[r, v])
// 1 thread per column -> every warp load/store is a full coalesced 128B line.
// Rank sum staged in 16-entry register arrays to force MLP=16 per thread.
__global__ __launch_bounds__(64)
void fftlm_outer_kernel(const float* __restrict__ Vh,
                        float* __restrict__ out) {
    __shared__ float s_sh[N_TOK];
    if (threadIdx.x < N_TOK) s_sh[threadIdx.x] = g_s[threadIdx.x];
    __syncthreads();

    const int col = blockIdx.x * 64 + threadIdx.x;
    if (col >= VOCAB) return;

    const float* p = Vh + col;
    float acc = 0.f;
#pragma unroll
    for (int base = 0; base < RANK; base += 16) {
        float buf[16];
#pragma unroll
        for (int i = 0; i < 16; i++)
            buf[i] = p[(size_t)(base + i) * VOCAB];
#pragma unroll
        for (int i = 0; i < 16; i++) acc += buf[i];
    }

    float* q = out + col;
#pragma unroll
    for (int n = 0; n < N_TOK; n++)
        q[(size_t)n * VOCAB] = s_sh[n] * acc;
}

extern "C" void kernel_launch(void* const* d_in, const int* in_sizes, int n_in,
                              void* d_out, int out_size) {
    const float* h  = (const float*)d_in[0];  // (32, 2048)
    const float* U  = (const float*)d_in[1];  // (2048, 64)
    const float* S  = (const float*)d_in[2];  // (64,)
    const float* Vh = (const float*)d_in[3];  // (64, 50257)
    float* out = (float*)d_out;               // (32, 50257)

    fftlm_partial_kernel<<<NBLK_PART, 256>>>(h, U, S);

    const int blocks = (VOCAB + 63) / 64;     // 786
    fftlm_outer_kernel<<<blocks, 64>>>(Vh, out);
}